// round 9
// baseline (speedup 1.0000x reference)
#include <cuda_runtime.h>
#include <math.h>

#define PNT 20
#define KNN 8
#define D0  128
#define MAXN 8192
typedef unsigned long long ull;

__device__ float g_act[ (size_t)MAXN*PNT*512 ];   // activations (widest 512)
__device__ float g_tmp[ (size_t)MAXN*PNT*256 ];   // xagg / xw scratch (widest 256)
__device__ float g_nm [ (size_t)MAXN*PNT*PNT ];   // layer-3 adjacency

__device__ __forceinline__ ull pack2f(float x, float y){
    return ((ull)__float_as_uint(y) << 32) | (ull)__float_as_uint(x);
}
__device__ __forceinline__ ull ffma2(ull a, ull b, ull c){
    ull d;
    asm("fma.rn.f32x2 %0, %1, %2, %3;" : "=l"(d) : "l"(a), "l"(b), "l"(c));
    return d;
}
__device__ __forceinline__ float lo2(ull v){ return __uint_as_float((unsigned)(v & 0xffffffffull)); }
__device__ __forceinline__ float hi2(ull v){ return __uint_as_float((unsigned)(v >> 32)); }
__device__ __forceinline__ float warp_sum(float v){
    #pragma unroll
    for(int m=16;m>0;m>>=1) v += __shfl_xor_sync(0xffffffffu, v, m);
    return v;
}

// ============================================================================
// sgemm: C[M,N] = A[M,K] @ B[K,N] (+bias, relu if EPI). 128x128x16 tiles,
// double buffered. B stored DUPLICATED in smem so the inner loop is pure
// LDS.128 + ffma2 (no pack movs): 6 LDS + 32 ffma2 per k.
// ============================================================================
template<bool EPI>
__global__ void __launch_bounds__(256,2)
sgemm_kernel(const float* __restrict__ A, const float* __restrict__ B,
             const float* __restrict__ bias, float* __restrict__ C,
             int M, int N, int K)
{
    __shared__ float As[2][16][128];      // transposed: As[k][m]
    __shared__ ull   Bs[2][16][128];      // duplicated: Bs[k][n] = (b,b)
    const int tid = threadIdx.x;
    const int m0 = blockIdx.y * 128, n0 = blockIdx.x * 128;
    const int tx = tid & 15, ty = tid >> 4;
    const int ar = tid >> 2, ac = (tid & 3) * 4;   // A: rows ar, ar+64; cols ac..ac+3
    const int br = tid >> 5, bc = (tid & 31) * 4;  // B: rows br, br+8

    const float* Ag = A + (long long)(m0 + ar) * K + ac;
    const float* Bg = B + (long long)br * N + (n0 + bc);

    // prologue: tile 0
    {
        float4 a0 = *(const float4*)(Ag);
        float4 a1 = *(const float4*)(Ag + (long long)64 * K);
        float4 b0 = *(const float4*)(Bg);
        float4 b1 = *(const float4*)(Bg + (long long)8 * N);
        As[0][ac+0][ar] = a0.x; As[0][ac+1][ar] = a0.y;
        As[0][ac+2][ar] = a0.z; As[0][ac+3][ar] = a0.w;
        As[0][ac+0][ar+64] = a1.x; As[0][ac+1][ar+64] = a1.y;
        As[0][ac+2][ar+64] = a1.z; As[0][ac+3][ar+64] = a1.w;
        Bs[0][br  ][bc+0]=pack2f(b0.x,b0.x); Bs[0][br  ][bc+1]=pack2f(b0.y,b0.y);
        Bs[0][br  ][bc+2]=pack2f(b0.z,b0.z); Bs[0][br  ][bc+3]=pack2f(b0.w,b0.w);
        Bs[0][br+8][bc+0]=pack2f(b1.x,b1.x); Bs[0][br+8][bc+1]=pack2f(b1.y,b1.y);
        Bs[0][br+8][bc+2]=pack2f(b1.z,b1.z); Bs[0][br+8][bc+3]=pack2f(b1.w,b1.w);
    }
    __syncthreads();

    ull acc[4][8];
    #pragma unroll
    for(int r=0;r<4;r++){
        #pragma unroll
        for(int c=0;c<8;c++) acc[r][c]=0ull;
    }

    const int nk = K >> 4;
    for(int t=0;t<nk;t++){
        const int cur = t & 1;
        float4 na0,na1,nb0,nb1;
        if(t+1<nk){
            const float* Ag2 = Ag + (t+1)*16;
            const float* Bg2 = Bg + (long long)((t+1)*16) * N;
            na0 = *(const float4*)(Ag2);
            na1 = *(const float4*)(Ag2 + (long long)64 * K);
            nb0 = *(const float4*)(Bg2);
            nb1 = *(const float4*)(Bg2 + (long long)8 * N);
        }
        #pragma unroll
        for(int k=0;k<16;k++){
            ulonglong2 p0 = *(const ulonglong2*)&As[cur][k][ty*8];
            ulonglong2 p1 = *(const ulonglong2*)&As[cur][k][ty*8+4];
            ulonglong2 w01 = *(const ulonglong2*)&Bs[cur][k][tx*8+0];
            ulonglong2 w23 = *(const ulonglong2*)&Bs[cur][k][tx*8+2];
            ulonglong2 w45 = *(const ulonglong2*)&Bs[cur][k][tx*8+4];
            ulonglong2 w67 = *(const ulonglong2*)&Bs[cur][k][tx*8+6];
            ull a2[4] = {p0.x, p0.y, p1.x, p1.y};
            ull ww[8] = {w01.x,w01.y,w23.x,w23.y,w45.x,w45.y,w67.x,w67.y};
            #pragma unroll
            for(int c=0;c<8;c++){
                #pragma unroll
                for(int r=0;r<4;r++) acc[r][c] = ffma2(a2[r], ww[c], acc[r][c]);
            }
        }
        if(t+1<nk){
            const int nxt = cur ^ 1;
            As[nxt][ac+0][ar] = na0.x; As[nxt][ac+1][ar] = na0.y;
            As[nxt][ac+2][ar] = na0.z; As[nxt][ac+3][ar] = na0.w;
            As[nxt][ac+0][ar+64] = na1.x; As[nxt][ac+1][ar+64] = na1.y;
            As[nxt][ac+2][ar+64] = na1.z; As[nxt][ac+3][ar+64] = na1.w;
            Bs[nxt][br  ][bc+0]=pack2f(nb0.x,nb0.x); Bs[nxt][br  ][bc+1]=pack2f(nb0.y,nb0.y);
            Bs[nxt][br  ][bc+2]=pack2f(nb0.z,nb0.z); Bs[nxt][br  ][bc+3]=pack2f(nb0.w,nb0.w);
            Bs[nxt][br+8][bc+0]=pack2f(nb1.x,nb1.x); Bs[nxt][br+8][bc+1]=pack2f(nb1.y,nb1.y);
            Bs[nxt][br+8][bc+2]=pack2f(nb1.z,nb1.z); Bs[nxt][br+8][bc+3]=pack2f(nb1.w,nb1.w);
        }
        __syncthreads();
    }

    // epilogue: optional bias+relu, write 8x8
    float bz[8];
    if(EPI){
        float4 q0 = *(const float4*)(bias + n0 + tx*8);
        float4 q1 = *(const float4*)(bias + n0 + tx*8 + 4);
        bz[0]=q0.x; bz[1]=q0.y; bz[2]=q0.z; bz[3]=q0.w;
        bz[4]=q1.x; bz[5]=q1.y; bz[6]=q1.z; bz[7]=q1.w;
    }
    #pragma unroll
    for(int r=0;r<4;r++){
        float vl[8], vh[8];
        #pragma unroll
        for(int c=0;c<8;c++){
            float lo = lo2(acc[r][c]), hi = hi2(acc[r][c]);
            if(EPI){ lo = fmaxf(lo + bz[c], 0.f); hi = fmaxf(hi + bz[c], 0.f); }
            vl[c]=lo; vh[c]=hi;
        }
        float* c0 = C + (long long)(m0 + ty*8 + 2*r    ) * N + n0 + tx*8;
        float* c1 = C + (long long)(m0 + ty*8 + 2*r + 1) * N + n0 + tx*8;
        *(float4*)(c0)   = make_float4(vl[0],vl[1],vl[2],vl[3]);
        *(float4*)(c0+4) = make_float4(vl[4],vl[5],vl[6],vl[7]);
        *(float4*)(c1)   = make_float4(vh[0],vh[1],vh[2],vh[3]);
        *(float4*)(c1+4) = make_float4(vh[4],vh[5],vh[6],vh[7]);
    }
}

// ============================================================================
// graph kernel: Gram -> kNN -> NmT. If AGG: also computes Xagg = Nm @ Ap and
// writes it (outp = xagg buffer). Else writes NmT to gmem (outp = nm buffer).
// Pair indices decoded ONCE into smem tables (kills the per-iteration ALU).
// ============================================================================
template<int IN, bool AGG>
__global__ void __launch_bounds__(256)
graph_kernel(const float* __restrict__ act, float* __restrict__ outp)
{
    __shared__ ull   NmP[PNT*PNT];        // packed Nm (also scratch ordering: 8B aligned first)
    __shared__ float Ap[PNT*IN];          // points-major: Ap[p*IN + f]
    __shared__ float G[PNT*PNT];
    __shared__ float NmT[PNT*PNT];        // NmT[s*PNT + t]
    __shared__ unsigned char pii[210], pjj[210];
    __shared__ int   knn[PNT*KNN];
    __shared__ int   deg[PNT];
    __shared__ float dinv[PNT];

    const int tid = threadIdx.x, warp = tid >> 5, lane = tid & 31;
    const long long b = blockIdx.x;

    // pair index tables (i<=j incl diagonal), decoded once
    if(tid < 210){
        int i=0, rem=tid;
        while(rem >= PNT-i){ rem -= PNT-i; i++; }
        pii[tid]=(unsigned char)i; pjj[tid]=(unsigned char)(i+rem);
    }
    // load sample
    {
        const float4* src4 = (const float4*)(act + b*(long long)(PNT*IN));
        float4* Ap4 = (float4*)Ap;
        for(int q=tid;q<PNT*IN/4;q+=256) Ap4[q]=src4[q];
    }
    __syncthreads();

    // Gram: 210 pairs, 4 in flight per warp (pipelined shfl reductions)
    for(int q0 = warp*4; q0 < 210; q0 += 32){
        int ii[4], jj[4]; float accv[4];
        #pragma unroll
        for(int u=0;u<4;u++){
            int q = q0+u; if(q >= 210) q = 0;
            ii[u]=pii[q]; jj[u]=pjj[q];
        }
        #pragma unroll
        for(int u=0;u<4;u++){
            const float4* ri = (const float4*)&Ap[ii[u]*IN];
            const float4* rj = (const float4*)&Ap[jj[u]*IN];
            float s = 0.f;
            #pragma unroll
            for(int c=0;c<IN/128;c++){
                float4 av = ri[lane + c*32], bv = rj[lane + c*32];
                s = fmaf(av.x,bv.x,s); s = fmaf(av.y,bv.y,s);
                s = fmaf(av.z,bv.z,s); s = fmaf(av.w,bv.w,s);
            }
            accv[u]=s;
        }
        #pragma unroll
        for(int u=0;u<4;u++) accv[u]=warp_sum(accv[u]);
        if(lane==0){
            #pragma unroll
            for(int u=0;u<4;u++) if(q0+u<210){
                G[ii[u]*PNT+jj[u]] = accv[u];
                G[jj[u]*PNT+ii[u]] = accv[u];
            }
        }
    }
    __syncthreads();

    // stable K-smallest per row, computed straight from G
    // d2[i][j] = G_ii + G_jj - 2*G_ij (exact reference formula); self -> -inf
    if(tid<PNT){
        const int i = tid;
        const float gii = G[i*PNT+i];
        float row[PNT];
        #pragma unroll
        for(int j=0;j<PNT;j++)
            row[j] = (j==i) ? __int_as_float(0xff800000)
                            : gii + G[j*PNT+j] - 2.f*G[i*PNT+j];
        unsigned used=0;
        #pragma unroll
        for(int k=0;k<KNN+1;k++){
            float best = __int_as_float(0x7f800000); int bj=0;
            #pragma unroll
            for(int j=0;j<PNT;j++){
                if( !((used>>j)&1u) && row[j] < best ){ best=row[j]; bj=j; }
            }
            used |= 1u<<bj;
            if(k>0) knn[tid*KNN + (k-1)] = bj;     // first pick = self, dropped
        }
        deg[tid]=1;    // self loop
    }
    for(int q=tid;q<PNT*PNT;q+=256) NmT[q]=0.f;
    __syncthreads();
    if(tid<PNT*KNN) atomicAdd(&deg[knn[tid]], 1);
    __syncthreads();
    if(tid<PNT) dinv[tid] = 1.f/sqrtf((float)deg[tid]);
    __syncthreads();
    if(tid<PNT*KNN){
        int u = tid>>3;            // source
        int t = knn[tid];          // target
        NmT[u*PNT+t] = dinv[t]*dinv[u];
    }
    if(tid<PNT) NmT[tid*PNT+tid] = dinv[tid]*dinv[tid];
    __syncthreads();

    if(!AGG){
        for(int q=tid;q<PNT*PNT;q+=256) outp[b*(PNT*PNT) + q] = NmT[q];
        return;
    }

    // Xagg[t][f] = sum_s Nm[t][s] * Ap[s][f], Nm[t][s] = NmT[s*PNT+t]
    for(int q=tid;q<PNT*PNT;q+=256){ float v=NmT[q]; NmP[q]=pack2f(v,v); }
    __syncthreads();
    if(2*tid < IN){
        const int f2 = tid;        // column pair
        ull acc[PNT];
        #pragma unroll
        for(int t=0;t<PNT;t++) acc[t]=0ull;
        #pragma unroll 2
        for(int s=0;s<PNT;s++){
            ull av = *(const ull*)&Ap[s*IN + 2*f2];
            const ull* nrow = &NmP[s*PNT];
            #pragma unroll
            for(int t=0;t<PNT;t++) acc[t] = ffma2(av, nrow[t], acc[t]);
        }
        float* dst = outp + b*(long long)(PNT*IN);
        #pragma unroll
        for(int t=0;t<PNT;t++) *(ull*)&dst[t*IN + 2*f2] = acc[t];
    }
}

// ============================================================================
// aggregate (layer 3, post-GEMM): act[b][t][o] = relu(sum_s NmT[s][t]*xw[b][s][o] + b3[o])
// ============================================================================
template<int OUT>
__global__ void __launch_bounds__(256)
aggregate_kernel(const float* __restrict__ xw, const float* __restrict__ nm,
                 const float* __restrict__ bias, float* __restrict__ act)
{
    __shared__ __align__(16) float NmT[PNT*PNT];
    const int tid = threadIdx.x;
    const long long b = blockIdx.x;
    for(int q=tid;q<PNT*PNT;q+=256) NmT[q]=nm[b*(PNT*PNT)+q];
    __syncthreads();

    const float* xwb  = xw  + b*(long long)(PNT*OUT);
    float*       actb = act + b*(long long)(PNT*OUT);
    if(tid >= OUT) return;
    const int o = tid;
    ull acc[PNT/2];
    #pragma unroll
    for(int th=0;th<PNT/2;th++) acc[th]=0ull;
    #pragma unroll 2
    for(int s=0;s<PNT;s++){
        const ull* nrow = (const ull*)&NmT[s*PNT];
        float v = xwb[s*OUT + o];
        ull vv = pack2f(v,v);
        #pragma unroll
        for(int th=0;th<PNT/2;th++) acc[th]=ffma2(nrow[th], vv, acc[th]);
    }
    float bo = bias[o];
    #pragma unroll
    for(int th=0;th<PNT/2;th++){
        actb[(2*th  )*OUT + o] = fmaxf(lo2(acc[th]) + bo, 0.f);
        actb[(2*th+1)*OUT + o] = fmaxf(hi2(acc[th]) + bo, 0.f);
    }
}

// ============================================================================
// head: mean pool -> fc 128x64 relu -> fc 64x3 -> softmax
// ============================================================================
__global__ void __launch_bounds__(128)
head_kernel(const float* __restrict__ act,
            const float* __restrict__ W4, const float* __restrict__ b4,
            const float* __restrict__ W5, const float* __restrict__ b5,
            float* __restrict__ out)
{
    __shared__ float msm[128], hsm[64], lsm[3];
    const int tid = threadIdx.x;
    const long long b = blockIdx.x;
    const float* ab = act + b*(long long)(PNT*128);
    {
        float s=0.f;
        #pragma unroll
        for(int p=0;p<PNT;p++) s += ab[p*128 + tid];
        msm[tid] = s * (1.f/PNT);
    }
    __syncthreads();
    if(tid<64){
        float a=b4[tid];
        #pragma unroll 4
        for(int f=0;f<128;f++) a = fmaf(msm[f], W4[f*64+tid], a);
        hsm[tid]=fmaxf(a,0.f);
    }
    __syncthreads();
    if(tid<3){
        float a=b5[tid];
        #pragma unroll
        for(int j=0;j<64;j++) a = fmaf(hsm[j], W5[j*3+tid], a);
        lsm[tid]=a;
    }
    __syncthreads();
    if(tid==0){
        float l0=lsm[0], l1=lsm[1], l2=lsm[2];
        float m=fmaxf(l0,fmaxf(l1,l2));
        float e0=expf(l0-m), e1=expf(l1-m), e2=expf(l2-m);
        float s=e0+e1+e2;
        out[b*3+0]=e0/s; out[b*3+1]=e1/s; out[b*3+2]=e2/s;
    }
}

extern "C" void kernel_launch(void* const* d_in, const int* in_sizes, int n_in,
                              void* d_out, int out_size){
    const float* x  = (const float*)d_in[0];
    const float* W1 = (const float*)d_in[1];
    const float* b1 = (const float*)d_in[2];
    const float* W2 = (const float*)d_in[3];
    const float* b2 = (const float*)d_in[4];
    const float* W3 = (const float*)d_in[5];
    const float* b3 = (const float*)d_in[6];
    const float* W4 = (const float*)d_in[7];
    const float* b4 = (const float*)d_in[8];
    const float* W5 = (const float*)d_in[9];
    const float* b5 = (const float*)d_in[10];
    float* out = (float*)d_out;

    const int NS = in_sizes[0]/(PNT*D0);   // 8192
    const int M  = NS*PNT;                 // 163840

    float *act, *tmp, *nm;
    cudaGetSymbolAddress((void**)&act, g_act);
    cudaGetSymbolAddress((void**)&tmp, g_tmp);
    cudaGetSymbolAddress((void**)&nm,  g_nm);

    // layer 1: aggregate-before (xagg = Nm@x), then GEMM+bias+relu
    graph_kernel<128,true><<<NS,256>>>(x, tmp);
    sgemm_kernel<true><<<dim3(2, M/128),256>>>(tmp, W1, b1, act, M, 256, 128);
    // layer 2: aggregate-before
    graph_kernel<256,true><<<NS,256>>>(act, tmp);
    sgemm_kernel<true><<<dim3(4, M/128),256>>>(tmp, W2, b2, act, M, 512, 256);
    // layer 3: aggregate-after (512 -> 128)
    graph_kernel<512,false><<<NS,256>>>(act, nm);
    sgemm_kernel<false><<<dim3(1, M/128),256>>>(act, W3, (const float*)0, tmp, M, 128, 512);
    aggregate_kernel<128><<<NS,256>>>(tmp, nm, b3, act);
    // head
    head_kernel<<<NS,128>>>(act, W4, b4, W5, b5, out);
}

// round 10
// speedup vs baseline: 2.2542x; 2.2542x over previous
#include <cuda_runtime.h>
#include <math.h>

#define PNT 20
#define KNN 8
#define D0  128
#define MAXN 8192
typedef unsigned long long ull;

__device__ float g_act[ (size_t)MAXN*PNT*512 ];   // activations (widest 512)
__device__ float g_tmp[ (size_t)MAXN*PNT*512 ];   // xagg scratch (widest 512)

__device__ __forceinline__ ull pack2f(float x, float y){
    return ((ull)__float_as_uint(y) << 32) | (ull)__float_as_uint(x);
}
__device__ __forceinline__ ull ffma2(ull a, ull b, ull c){
    ull d;
    asm("fma.rn.f32x2 %0, %1, %2, %3;" : "=l"(d) : "l"(a), "l"(b), "l"(c));
    return d;
}
__device__ __forceinline__ float lo2(ull v){ return __uint_as_float((unsigned)(v & 0xffffffffull)); }
__device__ __forceinline__ float hi2(ull v){ return __uint_as_float((unsigned)(v >> 32)); }
__device__ __forceinline__ float warp_sum(float v){
    #pragma unroll
    for(int m=16;m>0;m>>=1) v += __shfl_xor_sync(0xffffffffu, v, m);
    return v;
}

// ============================================================================
// sgemm: C[M,N] = A[M,K] @ B[K,N] (+bias+relu if EPI). 128x128x16 tiles,
// double buffered. Conflict-free warp tiling: 8 warps = 4(m) x 2(n),
// warp tile 32x64, lanes 4(m) x 8(n). A fragments are natural (m,m+1) ull
// pairs (broadcast LDS.128, banks 0-15), B fragments float4 (banks 0-31).
// Inner loop per k: 4 LDS.128 + 8 MOV-pack + 32 ffma2 -> FMA-pipe bound.
// ============================================================================
template<bool EPI>
__global__ void __launch_bounds__(256,2)
sgemm_kernel(const float* __restrict__ A, const float* __restrict__ B,
             const float* __restrict__ bias, float* __restrict__ C,
             int M, int N, int K)
{
    __shared__ __align__(16) float As[2][16][132];   // transposed + pad: As[k][m]
    __shared__ __align__(16) float Bs[2][16][128];   // Bs[k][n]
    const int tid = threadIdx.x;
    const int warp = tid >> 5, lane = tid & 31;
    const int wm = warp >> 1, wn = warp & 1;         // warp grid 4(m) x 2(n)
    const int lm = lane & 3,  ln = lane >> 2;        // lane grid 4(m) x 8(n)
    const int m0 = blockIdx.y * 128, n0 = blockIdx.x * 128;
    const int ar = tid >> 2, ac = (tid & 3) * 4;     // A loader: rows ar, ar+64
    const int br = tid >> 5, bc = (tid & 31) * 4;    // B loader: rows br, br+8

    const float* Ag = A + (long long)(m0 + ar) * K + ac;
    const float* Bg = B + (long long)br * N + (n0 + bc);

    // prologue: tile 0
    {
        float4 a0 = *(const float4*)(Ag);
        float4 a1 = *(const float4*)(Ag + (long long)64 * K);
        float4 b0 = *(const float4*)(Bg);
        float4 b1 = *(const float4*)(Bg + (long long)8 * N);
        As[0][ac+0][ar] = a0.x; As[0][ac+1][ar] = a0.y;
        As[0][ac+2][ar] = a0.z; As[0][ac+3][ar] = a0.w;
        As[0][ac+0][ar+64] = a1.x; As[0][ac+1][ar+64] = a1.y;
        As[0][ac+2][ar+64] = a1.z; As[0][ac+3][ar+64] = a1.w;
        *(float4*)&Bs[0][br  ][bc] = b0;
        *(float4*)&Bs[0][br+8][bc] = b1;
    }
    __syncthreads();

    ull acc[4][8];   // [m-pair][n]: pairs (m0,m0+1),(m0+2,+3),(+16,+17),(+18,+19)
    #pragma unroll
    for(int r=0;r<4;r++){
        #pragma unroll
        for(int c=0;c<8;c++) acc[r][c]=0ull;
    }

    const int mb = wm*32 + lm*4;     // this thread's m base within tile
    const int nb = wn*64 + ln*4;     // this thread's n base within tile

    const int nk = K >> 4;
    for(int t=0;t<nk;t++){
        const int cur = t & 1;
        float4 na0,na1,nb0,nb1;
        if(t+1<nk){
            const float* Ag2 = Ag + (t+1)*16;
            const float* Bg2 = Bg + (long long)((t+1)*16) * N;
            na0 = *(const float4*)(Ag2);
            na1 = *(const float4*)(Ag2 + (long long)64 * K);
            nb0 = *(const float4*)(Bg2);
            nb1 = *(const float4*)(Bg2 + (long long)8 * N);
        }
        #pragma unroll
        for(int k=0;k<16;k++){
            ulonglong2 a01 = *(const ulonglong2*)&As[cur][k][mb];      // (m0,m1),(m2,m3)
            ulonglong2 a23 = *(const ulonglong2*)&As[cur][k][mb+16];   // (+16,+17),(+18,+19)
            float4 q0 = *(const float4*)&Bs[cur][k][nb];
            float4 q1 = *(const float4*)&Bs[cur][k][nb+32];
            ull am[4] = {a01.x, a01.y, a23.x, a23.y};
            float bb[8] = {q0.x,q0.y,q0.z,q0.w, q1.x,q1.y,q1.z,q1.w};
            #pragma unroll
            for(int c=0;c<8;c++){
                ull w = pack2f(bb[c], bb[c]);
                #pragma unroll
                for(int r=0;r<4;r++) acc[r][c] = ffma2(am[r], w, acc[r][c]);
            }
        }
        if(t+1<nk){
            const int nxt = cur ^ 1;
            As[nxt][ac+0][ar] = na0.x; As[nxt][ac+1][ar] = na0.y;
            As[nxt][ac+2][ar] = na0.z; As[nxt][ac+3][ar] = na0.w;
            As[nxt][ac+0][ar+64] = na1.x; As[nxt][ac+1][ar+64] = na1.y;
            As[nxt][ac+2][ar+64] = na1.z; As[nxt][ac+3][ar+64] = na1.w;
            *(float4*)&Bs[nxt][br  ][bc] = nb0;
            *(float4*)&Bs[nxt][br+8][bc] = nb1;
        }
        __syncthreads();
    }

    // epilogue: optional bias+relu, write 8 rows x 8 cols
    float bz[8];
    if(EPI){
        float4 q0 = *(const float4*)(bias + n0 + nb);
        float4 q1 = *(const float4*)(bias + n0 + nb + 32);
        bz[0]=q0.x; bz[1]=q0.y; bz[2]=q0.z; bz[3]=q0.w;
        bz[4]=q1.x; bz[5]=q1.y; bz[6]=q1.z; bz[7]=q1.w;
    }
    #pragma unroll
    for(int r=0;r<4;r++){
        const int row_lo = m0 + mb + (r&1)*2 + (r>>1)*16;
        float vl[8], vh[8];
        #pragma unroll
        for(int c=0;c<8;c++){
            float lo = lo2(acc[r][c]), hi = hi2(acc[r][c]);
            if(EPI){ lo = fmaxf(lo + bz[c], 0.f); hi = fmaxf(hi + bz[c], 0.f); }
            vl[c]=lo; vh[c]=hi;
        }
        float* c0 = C + (long long)(row_lo    ) * N + n0 + nb;
        float* c1 = C + (long long)(row_lo + 1) * N + n0 + nb;
        *(float4*)(c0)    = make_float4(vl[0],vl[1],vl[2],vl[3]);
        *(float4*)(c0+32) = make_float4(vl[4],vl[5],vl[6],vl[7]);
        *(float4*)(c1)    = make_float4(vh[0],vh[1],vh[2],vh[3]);
        *(float4*)(c1+32) = make_float4(vh[4],vh[5],vh[6],vh[7]);
    }
}

// ============================================================================
// graph kernel: Gram -> kNN -> NmT -> Xagg = Nm @ Ap  (aggregate-before).
// Pair indices decoded once into smem tables.
// ============================================================================
template<int IN>
__global__ void __launch_bounds__(256)
graph_kernel(const float* __restrict__ act, float* __restrict__ outp)
{
    __shared__ ull   NmP[PNT*PNT];        // packed Nm rows (v,v)
    __shared__ float Ap[PNT*IN];          // points-major: Ap[p*IN + f]
    __shared__ float G[PNT*PNT];
    __shared__ float NmT[PNT*PNT];        // NmT[s*PNT + t]
    __shared__ unsigned char pii[210], pjj[210];
    __shared__ int   knn[PNT*KNN];
    __shared__ int   deg[PNT];
    __shared__ float dinv[PNT];

    const int tid = threadIdx.x, warp = tid >> 5, lane = tid & 31;
    const long long b = blockIdx.x;

    // pair index tables (i<=j incl diagonal), decoded once
    if(tid < 210){
        int i=0, rem=tid;
        while(rem >= PNT-i){ rem -= PNT-i; i++; }
        pii[tid]=(unsigned char)i; pjj[tid]=(unsigned char)(i+rem);
    }
    // load sample
    {
        const float4* src4 = (const float4*)(act + b*(long long)(PNT*IN));
        float4* Ap4 = (float4*)Ap;
        for(int q=tid;q<PNT*IN/4;q+=256) Ap4[q]=src4[q];
    }
    __syncthreads();

    // Gram: 210 pairs, 4 in flight per warp (pipelined shfl reductions)
    for(int q0 = warp*4; q0 < 210; q0 += 32){
        int ii[4], jj[4]; float accv[4];
        #pragma unroll
        for(int u=0;u<4;u++){
            int q = q0+u; if(q >= 210) q = 0;
            ii[u]=pii[q]; jj[u]=pjj[q];
        }
        #pragma unroll
        for(int u=0;u<4;u++){
            const float4* ri = (const float4*)&Ap[ii[u]*IN];
            const float4* rj = (const float4*)&Ap[jj[u]*IN];
            float s = 0.f;
            #pragma unroll
            for(int c=0;c<IN/128;c++){
                float4 av = ri[lane + c*32], bv = rj[lane + c*32];
                s = fmaf(av.x,bv.x,s); s = fmaf(av.y,bv.y,s);
                s = fmaf(av.z,bv.z,s); s = fmaf(av.w,bv.w,s);
            }
            accv[u]=s;
        }
        #pragma unroll
        for(int u=0;u<4;u++) accv[u]=warp_sum(accv[u]);
        if(lane==0){
            #pragma unroll
            for(int u=0;u<4;u++) if(q0+u<210){
                G[ii[u]*PNT+jj[u]] = accv[u];
                G[jj[u]*PNT+ii[u]] = accv[u];
            }
        }
    }
    __syncthreads();

    // stable K-smallest per row from G:
    // d2[i][j] = G_ii + G_jj - 2*G_ij (exact reference formula); self -> -inf
    if(tid<PNT){
        const int i = tid;
        const float gii = G[i*PNT+i];
        float row[PNT];
        #pragma unroll
        for(int j=0;j<PNT;j++)
            row[j] = (j==i) ? __int_as_float(0xff800000)
                            : gii + G[j*PNT+j] - 2.f*G[i*PNT+j];
        unsigned used=0;
        #pragma unroll
        for(int k=0;k<KNN+1;k++){
            float best = __int_as_float(0x7f800000); int bj=0;
            #pragma unroll
            for(int j=0;j<PNT;j++){
                if( !((used>>j)&1u) && row[j] < best ){ best=row[j]; bj=j; }
            }
            used |= 1u<<bj;
            if(k>0) knn[tid*KNN + (k-1)] = bj;     // first pick = self, dropped
        }
        deg[tid]=1;    // self loop
    }
    for(int q=tid;q<PNT*PNT;q+=256) NmT[q]=0.f;
    __syncthreads();
    if(tid<PNT*KNN) atomicAdd(&deg[knn[tid]], 1);
    __syncthreads();
    if(tid<PNT) dinv[tid] = 1.f/sqrtf((float)deg[tid]);
    __syncthreads();
    if(tid<PNT*KNN){
        int u = tid>>3;            // source
        int t = knn[tid];          // target
        NmT[u*PNT+t] = dinv[t]*dinv[u];
    }
    if(tid<PNT) NmT[tid*PNT+tid] = dinv[tid]*dinv[tid];
    __syncthreads();

    // Xagg[t][f] = sum_s Nm[t][s] * Ap[s][f], Nm[t][s] = NmT[s*PNT+t]
    for(int q=tid;q<PNT*PNT;q+=256){ float v=NmT[q]; NmP[q]=pack2f(v,v); }
    __syncthreads();
    for(int f2 = tid; 2*f2 < IN; f2 += 256){
        ull acc[PNT];
        #pragma unroll
        for(int t=0;t<PNT;t++) acc[t]=0ull;
        #pragma unroll 2
        for(int s=0;s<PNT;s++){
            ull av = *(const ull*)&Ap[s*IN + 2*f2];
            const ull* nrow = &NmP[s*PNT];
            #pragma unroll
            for(int t=0;t<PNT;t++) acc[t] = ffma2(av, nrow[t], acc[t]);
        }
        float* dst = outp + b*(long long)(PNT*IN);
        #pragma unroll
        for(int t=0;t<PNT;t++) *(ull*)&dst[t*IN + 2*f2] = acc[t];
    }
}

// ============================================================================
// head: mean pool -> fc 128x64 relu -> fc 64x3 -> softmax
// ============================================================================
__global__ void __launch_bounds__(128)
head_kernel(const float* __restrict__ act,
            const float* __restrict__ W4, const float* __restrict__ b4,
            const float* __restrict__ W5, const float* __restrict__ b5,
            float* __restrict__ out)
{
    __shared__ float msm[128], hsm[64], lsm[3];
    const int tid = threadIdx.x;
    const long long b = blockIdx.x;
    const float* ab = act + b*(long long)(PNT*128);
    {
        float s=0.f;
        #pragma unroll
        for(int p=0;p<PNT;p++) s += ab[p*128 + tid];
        msm[tid] = s * (1.f/PNT);
    }
    __syncthreads();
    if(tid<64){
        float a=b4[tid];
        #pragma unroll 4
        for(int f=0;f<128;f++) a = fmaf(msm[f], W4[f*64+tid], a);
        hsm[tid]=fmaxf(a,0.f);
    }
    __syncthreads();
    if(tid<3){
        float a=b5[tid];
        #pragma unroll
        for(int j=0;j<64;j++) a = fmaf(hsm[j], W5[j*3+tid], a);
        lsm[tid]=a;
    }
    __syncthreads();
    if(tid==0){
        float l0=lsm[0], l1=lsm[1], l2=lsm[2];
        float m=fmaxf(l0,fmaxf(l1,l2));
        float e0=expf(l0-m), e1=expf(l1-m), e2=expf(l2-m);
        float s=e0+e1+e2;
        out[b*3+0]=e0/s; out[b*3+1]=e1/s; out[b*3+2]=e2/s;
    }
}

extern "C" void kernel_launch(void* const* d_in, const int* in_sizes, int n_in,
                              void* d_out, int out_size){
    const float* x  = (const float*)d_in[0];
    const float* W1 = (const float*)d_in[1];
    const float* b1 = (const float*)d_in[2];
    const float* W2 = (const float*)d_in[3];
    const float* b2 = (const float*)d_in[4];
    const float* W3 = (const float*)d_in[5];
    const float* b3 = (const float*)d_in[6];
    const float* W4 = (const float*)d_in[7];
    const float* b4 = (const float*)d_in[8];
    const float* W5 = (const float*)d_in[9];
    const float* b5 = (const float*)d_in[10];
    float* out = (float*)d_out;

    const int NS = in_sizes[0]/(PNT*D0);   // 8192
    const int M  = NS*PNT;                 // 163840

    float *act, *tmp;
    cudaGetSymbolAddress((void**)&act, g_act);
    cudaGetSymbolAddress((void**)&tmp, g_tmp);

    // layer 1: xagg = Nm@x, then GEMM+bias+relu (aggregate-before)
    graph_kernel<128><<<NS,256>>>(x, tmp);
    sgemm_kernel<true><<<dim3(2, M/128),256>>>(tmp, W1, b1, act, M, 256, 128);
    // layer 2
    graph_kernel<256><<<NS,256>>>(act, tmp);
    sgemm_kernel<true><<<dim3(4, M/128),256>>>(tmp, W2, b2, act, M, 512, 256);
    // layer 3
    graph_kernel<512><<<NS,256>>>(act, tmp);
    sgemm_kernel<true><<<dim3(1, M/128),256>>>(tmp, W3, b3, act, M, 128, 512);
    // head
    head_kernel<<<NS,128>>>(act, W4, b4, W5, b5, out);
}

// round 11
// speedup vs baseline: 2.3360x; 1.0363x over previous
#include <cuda_runtime.h>
#include <math.h>

#define PNT 20
#define KNN 8
#define D0  128
#define MAXN 8192
typedef unsigned long long ull;

__device__ float g_act[ (size_t)MAXN*PNT*512 ];   // activations (widest 512)
__device__ float g_tmp[ (size_t)MAXN*PNT*512 ];   // xagg scratch (widest 512)

__device__ __forceinline__ ull pack2f(float x, float y){
    return ((ull)__float_as_uint(y) << 32) | (ull)__float_as_uint(x);
}
__device__ __forceinline__ ull ffma2(ull a, ull b, ull c){
    ull d;
    asm("fma.rn.f32x2 %0, %1, %2, %3;" : "=l"(d) : "l"(a), "l"(b), "l"(c));
    return d;
}
__device__ __forceinline__ float lo2(ull v){ return __uint_as_float((unsigned)(v & 0xffffffffull)); }
__device__ __forceinline__ float hi2(ull v){ return __uint_as_float((unsigned)(v >> 32)); }
__device__ __forceinline__ float warp_sum(float v){
    #pragma unroll
    for(int m=16;m>0;m>>=1) v += __shfl_xor_sync(0xffffffffu, v, m);
    return v;
}

// ============================================================================
// sgemm: C[M,N] = A[M,K] @ B[K,N] (+bias+relu if EPI). 128x128x16 tiles,
// double buffered. Conflict-free warp tiling: 8 warps = 4(m) x 2(n),
// warp tile 32x64, lanes 4(m) x 8(n).  (UNCHANGED from R10 — proven 69% fma.)
// ============================================================================
template<bool EPI>
__global__ void __launch_bounds__(256,2)
sgemm_kernel(const float* __restrict__ A, const float* __restrict__ B,
             const float* __restrict__ bias, float* __restrict__ C,
             int M, int N, int K)
{
    __shared__ __align__(16) float As[2][16][132];   // transposed + pad: As[k][m]
    __shared__ __align__(16) float Bs[2][16][128];   // Bs[k][n]
    const int tid = threadIdx.x;
    const int warp = tid >> 5, lane = tid & 31;
    const int wm = warp >> 1, wn = warp & 1;         // warp grid 4(m) x 2(n)
    const int lm = lane & 3,  ln = lane >> 2;        // lane grid 4(m) x 8(n)
    const int m0 = blockIdx.y * 128, n0 = blockIdx.x * 128;
    const int ar = tid >> 2, ac = (tid & 3) * 4;     // A loader: rows ar, ar+64
    const int br = tid >> 5, bc = (tid & 31) * 4;    // B loader: rows br, br+8

    const float* Ag = A + (long long)(m0 + ar) * K + ac;
    const float* Bg = B + (long long)br * N + (n0 + bc);

    {
        float4 a0 = *(const float4*)(Ag);
        float4 a1 = *(const float4*)(Ag + (long long)64 * K);
        float4 b0 = *(const float4*)(Bg);
        float4 b1 = *(const float4*)(Bg + (long long)8 * N);
        As[0][ac+0][ar] = a0.x; As[0][ac+1][ar] = a0.y;
        As[0][ac+2][ar] = a0.z; As[0][ac+3][ar] = a0.w;
        As[0][ac+0][ar+64] = a1.x; As[0][ac+1][ar+64] = a1.y;
        As[0][ac+2][ar+64] = a1.z; As[0][ac+3][ar+64] = a1.w;
        *(float4*)&Bs[0][br  ][bc] = b0;
        *(float4*)&Bs[0][br+8][bc] = b1;
    }
    __syncthreads();

    ull acc[4][8];
    #pragma unroll
    for(int r=0;r<4;r++){
        #pragma unroll
        for(int c=0;c<8;c++) acc[r][c]=0ull;
    }

    const int mb = wm*32 + lm*4;
    const int nb = wn*64 + ln*4;

    const int nk = K >> 4;
    for(int t=0;t<nk;t++){
        const int cur = t & 1;
        float4 na0,na1,nb0,nb1;
        if(t+1<nk){
            const float* Ag2 = Ag + (t+1)*16;
            const float* Bg2 = Bg + (long long)((t+1)*16) * N;
            na0 = *(const float4*)(Ag2);
            na1 = *(const float4*)(Ag2 + (long long)64 * K);
            nb0 = *(const float4*)(Bg2);
            nb1 = *(const float4*)(Bg2 + (long long)8 * N);
        }
        #pragma unroll
        for(int k=0;k<16;k++){
            ulonglong2 a01 = *(const ulonglong2*)&As[cur][k][mb];
            ulonglong2 a23 = *(const ulonglong2*)&As[cur][k][mb+16];
            float4 q0 = *(const float4*)&Bs[cur][k][nb];
            float4 q1 = *(const float4*)&Bs[cur][k][nb+32];
            ull am[4] = {a01.x, a01.y, a23.x, a23.y};
            float bb[8] = {q0.x,q0.y,q0.z,q0.w, q1.x,q1.y,q1.z,q1.w};
            #pragma unroll
            for(int c=0;c<8;c++){
                ull w = pack2f(bb[c], bb[c]);
                #pragma unroll
                for(int r=0;r<4;r++) acc[r][c] = ffma2(am[r], w, acc[r][c]);
            }
        }
        if(t+1<nk){
            const int nxt = cur ^ 1;
            As[nxt][ac+0][ar] = na0.x; As[nxt][ac+1][ar] = na0.y;
            As[nxt][ac+2][ar] = na0.z; As[nxt][ac+3][ar] = na0.w;
            As[nxt][ac+0][ar+64] = na1.x; As[nxt][ac+1][ar+64] = na1.y;
            As[nxt][ac+2][ar+64] = na1.z; As[nxt][ac+3][ar+64] = na1.w;
            *(float4*)&Bs[nxt][br  ][bc] = nb0;
            *(float4*)&Bs[nxt][br+8][bc] = nb1;
        }
        __syncthreads();
    }

    float bz[8];
    if(EPI){
        float4 q0 = *(const float4*)(bias + n0 + nb);
        float4 q1 = *(const float4*)(bias + n0 + nb + 32);
        bz[0]=q0.x; bz[1]=q0.y; bz[2]=q0.z; bz[3]=q0.w;
        bz[4]=q1.x; bz[5]=q1.y; bz[6]=q1.z; bz[7]=q1.w;
    }
    #pragma unroll
    for(int r=0;r<4;r++){
        const int row_lo = m0 + mb + (r&1)*2 + (r>>1)*16;
        float vl[8], vh[8];
        #pragma unroll
        for(int c=0;c<8;c++){
            float lo = lo2(acc[r][c]), hi = hi2(acc[r][c]);
            if(EPI){ lo = fmaxf(lo + bz[c], 0.f); hi = fmaxf(hi + bz[c], 0.f); }
            vl[c]=lo; vh[c]=hi;
        }
        float* c0 = C + (long long)(row_lo    ) * N + n0 + nb;
        float* c1 = C + (long long)(row_lo + 1) * N + n0 + nb;
        *(float4*)(c0)    = make_float4(vl[0],vl[1],vl[2],vl[3]);
        *(float4*)(c0+32) = make_float4(vl[4],vl[5],vl[6],vl[7]);
        *(float4*)(c1)    = make_float4(vh[0],vh[1],vh[2],vh[3]);
        *(float4*)(c1+32) = make_float4(vh[4],vh[5],vh[6],vh[7]);
    }
}

// ============================================================================
// graph kernel: Gram (ffma2) -> kNN -> packed NmP (overlaid on G's smem)
// -> Xagg = Nm @ Ap  (aggregate-before).
// ============================================================================
template<int IN>
__global__ void __launch_bounds__(256)
graph_kernel(const float* __restrict__ act, float* __restrict__ outp)
{
    __shared__ __align__(16) float Ap[PNT*IN];   // points-major: Ap[p*IN + f]
    __shared__ __align__(16) ull   buf[PNT*PNT]; // G (float, first 1600B) then NmP (ull)
    __shared__ unsigned char pii[210], pjj[210];
    __shared__ int   knn[PNT*KNN];
    __shared__ int   deg[PNT];
    __shared__ float dinv[PNT];

    float* G   = (float*)buf;    // live: gram .. knn-selection
    ull*   NmP = buf;            // live: after knn-selection

    const int tid = threadIdx.x, warp = tid >> 5, lane = tid & 31;
    const long long b = blockIdx.x;

    // pair index tables (i<=j incl diagonal), decoded once
    if(tid < 210){
        int i=0, rem=tid;
        while(rem >= PNT-i){ rem -= PNT-i; i++; }
        pii[tid]=(unsigned char)i; pjj[tid]=(unsigned char)(i+rem);
    }
    // load sample
    {
        const float4* src4 = (const float4*)(act + b*(long long)(PNT*IN));
        float4* Ap4 = (float4*)Ap;
        for(int q=tid;q<PNT*IN/4;q+=256) Ap4[q]=src4[q];
    }
    if(tid<PNT) deg[tid]=1;      // self loop
    __syncthreads();

    // Gram: 210 pairs, 4 in flight per warp, packed f32x2 dot bodies
    for(int q0 = warp*4; q0 < 210; q0 += 32){
        int ii[4], jj[4]; float accv[4];
        #pragma unroll
        for(int u=0;u<4;u++){
            int q = q0+u; if(q >= 210) q = 0;
            ii[u]=pii[q]; jj[u]=pjj[q];
        }
        #pragma unroll
        for(int u=0;u<4;u++){
            const ulonglong2* ri = (const ulonglong2*)&Ap[ii[u]*IN];
            const ulonglong2* rj = (const ulonglong2*)&Ap[jj[u]*IN];
            ull s0=0ull, s1=0ull;
            #pragma unroll
            for(int c=0;c<IN/128;c++){
                ulonglong2 av = ri[lane + c*32], bv = rj[lane + c*32];
                s0 = ffma2(av.x, bv.x, s0);
                s1 = ffma2(av.y, bv.y, s1);
            }
            accv[u] = (lo2(s0)+hi2(s0)) + (lo2(s1)+hi2(s1));
        }
        #pragma unroll
        for(int u=0;u<4;u++) accv[u]=warp_sum(accv[u]);
        if(lane==0){
            #pragma unroll
            for(int u=0;u<4;u++) if(q0+u<210){
                G[ii[u]*PNT+jj[u]] = accv[u];
                G[jj[u]*PNT+ii[u]] = accv[u];
            }
        }
    }
    __syncthreads();

    // stable K-smallest per row from G:
    // d2[i][j] = G_ii + G_jj - 2*G_ij (exact reference formula); self -> -inf
    if(tid<PNT){
        const int i = tid;
        const float gii = G[i*PNT+i];
        float row[PNT];
        #pragma unroll
        for(int j=0;j<PNT;j++)
            row[j] = (j==i) ? __int_as_float(0xff800000)
                            : gii + G[j*PNT+j] - 2.f*G[i*PNT+j];
        unsigned used=0;
        #pragma unroll
        for(int k=0;k<KNN+1;k++){
            float best = __int_as_float(0x7f800000); int bj=0;
            #pragma unroll
            for(int j=0;j<PNT;j++){
                if( !((used>>j)&1u) && row[j] < best ){ best=row[j]; bj=j; }
            }
            used |= 1u<<bj;
            if(k>0) knn[tid*KNN + (k-1)] = bj;     // first pick = self, dropped
        }
    }
    __syncthreads();                               // G dead from here; buf becomes NmP

    if(tid<PNT*KNN) atomicAdd(&deg[knn[tid]], 1);  // in-degree at targets
    for(int q=tid;q<PNT*PNT;q+=256) NmP[q]=0ull;
    __syncthreads();
    if(tid<PNT) dinv[tid] = rsqrtf((float)deg[tid]);
    __syncthreads();
    if(tid<PNT*KNN){
        int u = tid>>3;            // source
        int t = knn[tid];          // target
        float w = dinv[t]*dinv[u];
        NmP[u*PNT+t] = pack2f(w,w);
    }
    if(tid<PNT){ float w = dinv[tid]*dinv[tid]; NmP[tid*PNT+tid] = pack2f(w,w); }
    __syncthreads();

    // Xagg[t][f] = sum_s Nm[t][s] * Ap[s][f], Nm[t][s] = NmP[s*PNT+t]
    for(int f2 = tid; 2*f2 < IN; f2 += 256){
        ull acc[PNT];
        #pragma unroll
        for(int t=0;t<PNT;t++) acc[t]=0ull;
        #pragma unroll 2
        for(int s=0;s<PNT;s++){
            ull av = *(const ull*)&Ap[s*IN + 2*f2];
            const ull* nrow = &NmP[s*PNT];
            #pragma unroll
            for(int t=0;t<PNT;t++) acc[t] = ffma2(av, nrow[t], acc[t]);
        }
        float* dst = outp + b*(long long)(PNT*IN);
        #pragma unroll
        for(int t=0;t<PNT;t++) *(ull*)&dst[t*IN + 2*f2] = acc[t];
    }
}

// ============================================================================
// head: mean pool -> fc 128x64 relu -> fc 64x3 -> softmax
// ============================================================================
__global__ void __launch_bounds__(128)
head_kernel(const float* __restrict__ act,
            const float* __restrict__ W4, const float* __restrict__ b4,
            const float* __restrict__ W5, const float* __restrict__ b5,
            float* __restrict__ out)
{
    __shared__ float msm[128], hsm[64], lsm[3];
    const int tid = threadIdx.x;
    const long long b = blockIdx.x;
    const float* ab = act + b*(long long)(PNT*128);
    {
        float s=0.f;
        #pragma unroll
        for(int p=0;p<PNT;p++) s += ab[p*128 + tid];
        msm[tid] = s * (1.f/PNT);
    }
    __syncthreads();
    if(tid<64){
        float a=b4[tid];
        #pragma unroll 4
        for(int f=0;f<128;f++) a = fmaf(msm[f], W4[f*64+tid], a);
        hsm[tid]=fmaxf(a,0.f);
    }
    __syncthreads();
    if(tid<3){
        float a=b5[tid];
        #pragma unroll
        for(int j=0;j<64;j++) a = fmaf(hsm[j], W5[j*3+tid], a);
        lsm[tid]=a;
    }
    __syncthreads();
    if(tid==0){
        float l0=lsm[0], l1=lsm[1], l2=lsm[2];
        float m=fmaxf(l0,fmaxf(l1,l2));
        float e0=expf(l0-m), e1=expf(l1-m), e2=expf(l2-m);
        float s=e0+e1+e2;
        out[b*3+0]=e0/s; out[b*3+1]=e1/s; out[b*3+2]=e2/s;
    }
}

extern "C" void kernel_launch(void* const* d_in, const int* in_sizes, int n_in,
                              void* d_out, int out_size){
    const float* x  = (const float*)d_in[0];
    const float* W1 = (const float*)d_in[1];
    const float* b1 = (const float*)d_in[2];
    const float* W2 = (const float*)d_in[3];
    const float* b2 = (const float*)d_in[4];
    const float* W3 = (const float*)d_in[5];
    const float* b3 = (const float*)d_in[6];
    const float* W4 = (const float*)d_in[7];
    const float* b4 = (const float*)d_in[8];
    const float* W5 = (const float*)d_in[9];
    const float* b5 = (const float*)d_in[10];
    float* out = (float*)d_out;

    const int NS = in_sizes[0]/(PNT*D0);   // 8192
    const int M  = NS*PNT;                 // 163840

    float *act, *tmp;
    cudaGetSymbolAddress((void**)&act, g_act);
    cudaGetSymbolAddress((void**)&tmp, g_tmp);

    // layer 1: xagg = Nm@x, then GEMM+bias+relu (aggregate-before)
    graph_kernel<128><<<NS,256>>>(x, tmp);
    sgemm_kernel<true><<<dim3(2, M/128),256>>>(tmp, W1, b1, act, M, 256, 128);
    // layer 2
    graph_kernel<256><<<NS,256>>>(act, tmp);
    sgemm_kernel<true><<<dim3(4, M/128),256>>>(tmp, W2, b2, act, M, 512, 256);
    // layer 3
    graph_kernel<512><<<NS,256>>>(act, tmp);
    sgemm_kernel<true><<<dim3(1, M/128),256>>>(tmp, W3, b3, act, M, 128, 512);
    // head
    head_kernel<<<NS,128>>>(act, W4, b4, W5, b5, out);
}